// round 8
// baseline (speedup 1.0000x reference)
#include <cuda_runtime.h>
#include <cstdint>

// ============================================================================
// EdgeUpdate: out[e] = relu( concat(nf[src[e]]+nf[dst[e]], ef[e]) @ W^T + b )
// GEMM: M=E (640000), N=128, K=256. tf32 mma.m16n8k8, fp32 accumulate.
//
// R8: 256 threads = 4 groups x 2 warps. Group tile = 64 edges; warp tile
// 64x64 (N split) -> A read 2x, B read 2x = 256KB LDS/tile (was 384KB).
// K in 8 sub-phases of 32, double-buffered A (2 x 8KB per group); fills are
// split in two 4-row halves wrapped around the two q-steps of each sub-phase.
//
// A layout (32-k rows, 128B): 8 entries of 16B; entry(q,t) packs
//   k = {16q+t, +4, +8, +12}; e = ((q^(row&1))<<2) | (t ^ (((row>>1)&1)<<1) ^ q)
//   addr = row*128 + e*16 (+4p within entry).
// W layout (128-k rows, 512B) unchanged (R5-verified).
// ============================================================================

static constexpr int SMB_BIAS = 0;
static constexpr int SMB_W    = 512;                 // 2 x 65536
static constexpr int SMB_A    = 512 + 131072;        // 4 groups x 2 bufs x 8192
static constexpr int SM_BYTES = SMB_A + 4 * 16384;   // 197120

#define CVT_TF32(u, f) asm("cvt.rna.tf32.f32 %0, %1;" : "=r"(u) : "f"(f))

__device__ __forceinline__ void mma_tf32(float* d, uint32_t a0, uint32_t a1,
                                         uint32_t a2, uint32_t a3,
                                         uint32_t b0, uint32_t b1) {
    asm volatile(
        "mma.sync.aligned.m16n8k8.row.col.f32.tf32.tf32.f32 "
        "{%0,%1,%2,%3}, {%4,%5,%6,%7}, {%8,%9}, {%0,%1,%2,%3};"
        : "+f"(d[0]), "+f"(d[1]), "+f"(d[2]), "+f"(d[3])
        : "r"(a0), "r"(a1), "r"(a2), "r"(a3), "r"(b0), "r"(b1));
}

// W store: 128-k rows (8 chunks of 64B), chunk=q^(row&7), slot=t^(((q>>1)+(row>>1))&3)
__device__ __forceinline__ void store_w_chunk(char* wrow, int row, int kbase32,
                                              const float* x) {
    const int r7  = row & 7;
    const int rh2 = (row >> 1) & 3;
#pragma unroll
    for (int qp = 0; qp < 2; qp++) {
        const int q = kbase32 * 2 + qp;
        char* cp = wrow + ((q ^ r7) << 6);
#pragma unroll
        for (int tt = 0; tt < 4; tt++) {
            const int slot = (tt ^ (((q >> 1) + rh2) & 3));
            uint32_t u0, u1, u2, u3;
            CVT_TF32(u0, x[16 * qp + tt]);
            CVT_TF32(u1, x[16 * qp + tt + 4]);
            CVT_TF32(u2, x[16 * qp + tt + 8]);
            CVT_TF32(u3, x[16 * qp + tt + 12]);
            *(uint4*)(cp + slot * 16) = make_uint4(u0, u1, u2, u3);
        }
    }
}

__global__ void __launch_bounds__(256, 1)
edge_update_kernel(const float* __restrict__ nf,
                   const int* __restrict__ ei,      // int32[2*E] (JAX x64 off)
                   const float* __restrict__ ef,
                   const float* __restrict__ W,
                   const float* __restrict__ bias,
                   float* __restrict__ out, int E) {
    extern __shared__ char smem[];
    float* bsm = (float*)(smem + SMB_BIAS);
    char*  Ws  = smem + SMB_W;
    char*  As  = smem + SMB_A;

    const int tid = threadIdx.x;
    const int wid = tid >> 5;
    const int lid = tid & 31;
    const int g   = lid >> 2;
    const int t   = lid & 3;
    const int g1  = g & 1;
    const int gh  = (g >> 1) & 3;
    const int gid = wid >> 1;          // group 0..3
    const int w2  = wid & 1;           // warp in group = N half

    if (tid < 128) bsm[tid] = bias[tid];

    // ---- One-time: W -> packed tf32 smem (2 k-phase arrays) ----
    {
        const int row = tid & 127;
        const int p   = tid >> 7;
        char* wrow = Ws + p * 65536 + row * 512;
        const float* src = W + row * 256 + p * 128;
#pragma unroll 1
        for (int c = 0; c < 4; c++) {
            float x[32];
            const float4* sp = (const float4*)(src + c * 32);
#pragma unroll
            for (int i = 0; i < 8; i++) {
                float4 v = sp[i];
                x[4 * i] = v.x; x[4 * i + 1] = v.y;
                x[4 * i + 2] = v.z; x[4 * i + 3] = v.w;
            }
            store_w_chunk(wrow, row, c, x);
        }
    }
    __syncthreads();

    // ---- Fill-side constants ----
    const int r4  = lid >> 3;              // row within 4-row iter
    const int b16 = lid & 7;               // 16B column within 128B (32 k)
    const int qf  = b16 >> 2;
    const int pf  = b16 & 3;
    const uint32_t ebase = (uint32_t)((((((qf ^ (r4 & 1)) << 2) |
                         ((((r4 >> 1) & 1) << 1) ^ qf))) << 4) + pf * 4);
    const int fillrow0 = 32 * w2 + r4;     // + 4*idx

    char* Ag = As + gid * 16384;           // 2 buffers of 8192

    // ---- MMA-side constants ----
    const int elo = t ^ (((g >> 1) & 1) << 1);
    const char* aBase = Ag + g * 128;
    const char* wBase = Ws + (64 * w2 + g) * 512;
    const int barid = gid + 1;
    const int ntiles = (E + 255) >> 8;

    auto load_idx = [&](int base_e, int* sIl, int* dIl) {
#pragma unroll
        for (int idx = 0; idx < 8; idx++) {
            int e = base_e + fillrow0 + 4 * idx;
            int eg2 = (e < E) ? e : (E - 1);
            sIl[idx] = ei[eg2];
            dIl[idx] = ei[(size_t)E + eg2];
        }
    };
    auto ldg_nf_h = [&](const int* sIl, const int* dIl, int sub, int h, float* x) {
#pragma unroll
        for (int it = 0; it < 4; it++) {
            const int idx = 4 * h + it;
            const float4 a = *(const float4*)(nf + (size_t)sIl[idx] * 128 + sub * 32 + b16 * 4);
            const float4 b = *(const float4*)(nf + (size_t)dIl[idx] * 128 + sub * 32 + b16 * 4);
            x[4 * it]     = a.x + b.x; x[4 * it + 1] = a.y + b.y;
            x[4 * it + 2] = a.z + b.z; x[4 * it + 3] = a.w + b.w;
        }
    };
    auto ldg_ef_h = [&](int base_e, int sp, int h, float* x) {
#pragma unroll
        for (int it = 0; it < 4; it++) {
            const int idx = 4 * h + it;
            int e = base_e + fillrow0 + 4 * idx;
            int eg2 = (e < E) ? e : (E - 1);
            const float4 v = *(const float4*)(ef + (size_t)eg2 * 128 + sp * 32 + b16 * 4);
            x[4 * it]     = v.x; x[4 * it + 1] = v.y;
            x[4 * it + 2] = v.z; x[4 * it + 3] = v.w;
        }
    };
    auto sts_h = [&](int bsel, int h, const float* x) {
        char* base = Ag + bsel * 8192;
#pragma unroll
        for (int it = 0; it < 4; it++) {
            const int row = fillrow0 + 4 * (4 * h + it);
            char* p0 = base + row * 128 + ebase;
#pragma unroll
            for (int j = 0; j < 4; j++) {
                uint32_t u; CVT_TF32(u, x[4 * it + j]);
                *(uint32_t*)((uintptr_t)p0 ^ (unsigned)(j << 4)) = u;
            }
        }
    };
    // MMA one q-step (k=16): A buf bsel chunk q (0/1), W phase wph chunk qg (0..7)
    auto mma_q = [&](int bsel, int q, int wph, int qg, float (*acc)[8][4]) {
        const char* ab = aBase + bsel * 8192;
        const uint32_t eoff = (uint32_t)(((((q ^ g1) << 2) | (elo ^ q))) << 4);
        uint4 aL[4], aH[4];
#pragma unroll
        for (int i = 0; i < 4; i++) {
            aL[i] = *(const uint4*)(ab + i * 2048 + eoff);
            aH[i] = *(const uint4*)(ab + i * 2048 + 1024 + eoff);
        }
        const char* wb = wBase + wph * 65536 + ((qg ^ g) << 6) +
                         ((t ^ (((qg >> 1) + gh) & 3)) << 4);
#pragma unroll
        for (int jj = 0; jj < 8; jj++) {
            const uint4 bv = *(const uint4*)(wb + jj * 4096);
#pragma unroll
            for (int i = 0; i < 4; i++) {
                mma_tf32(acc[i][jj], aL[i].x, aH[i].x, aL[i].y, aH[i].y, bv.x, bv.y);
                mma_tf32(acc[i][jj], aL[i].z, aH[i].z, aL[i].w, aH[i].w, bv.z, bv.w);
            }
        }
    };

    // ---- Prologue: fill buf0 with sub0 (nf k 0-31) ----
    int tile = blockIdx.x;
    if (tile >= ntiles) return;
    int e0g = tile * 256 + gid * 64;
    int sI[8], dI[8];
    load_idx(e0g, sI, dI);
    float x0[16], x1[16];
    ldg_nf_h(sI, dI, 0, 0, x0); sts_h(0, 0, x0);
    ldg_nf_h(sI, dI, 0, 1, x1); sts_h(0, 1, x1);
    asm volatile("bar.sync %0, 64;" :: "r"(barid) : "memory");

    while (true) {
        float acc[4][8][4] = {};

        // segs 0-2: mma nf sub s; fill nf sub s+1
#pragma unroll
        for (int s = 0; s < 3; s++) {
            ldg_nf_h(sI, dI, s + 1, 0, x0);
            mma_q(s & 1, 0, 0, s * 2, acc);
            sts_h((s + 1) & 1, 0, x0);
            ldg_nf_h(sI, dI, s + 1, 1, x1);
            mma_q(s & 1, 1, 0, s * 2 + 1, acc);
            sts_h((s + 1) & 1, 1, x1);
            asm volatile("bar.sync %0, 64;" :: "r"(barid) : "memory");
        }

        // seg 3: mma nf sub3; fill ef sp0; reload indices for NEXT tile
        const int ntile = tile + gridDim.x;
        const int ne0g  = ntile * 256 + gid * 64;
        ldg_ef_h(e0g, 0, 0, x0);
        mma_q(1, 0, 0, 6, acc);
        sts_h(0, 0, x0);
        ldg_ef_h(e0g, 0, 1, x1);
        load_idx(ne0g, sI, dI);            // clamped; harmless past end
        mma_q(1, 1, 0, 7, acc);
        sts_h(0, 1, x1);
        asm volatile("bar.sync %0, 64;" :: "r"(barid) : "memory");

        // segs 4-6: mma ef sub s; fill ef sp s-3
#pragma unroll
        for (int s = 4; s < 7; s++) {
            ldg_ef_h(e0g, s - 3, 0, x0);
            mma_q(s & 1, 0, 1, (s - 4) * 2, acc);
            sts_h((s + 1) & 1, 0, x0);
            ldg_ef_h(e0g, s - 3, 1, x1);
            mma_q(s & 1, 1, 1, (s - 4) * 2 + 1, acc);
            sts_h((s + 1) & 1, 1, x1);
            asm volatile("bar.sync %0, 64;" :: "r"(barid) : "memory");
        }

        // seg 7: mma ef sub7; fill NEXT tile's nf sub0 -> buf0
        ldg_nf_h(sI, dI, 0, 0, x0);
        mma_q(1, 0, 1, 6, acc);
        sts_h(0, 0, x0);
        ldg_nf_h(sI, dI, 0, 1, x1);
        mma_q(1, 1, 1, 7, acc);
        sts_h(0, 1, x1);
        asm volatile("bar.sync %0, 64;" :: "r"(barid) : "memory");

        // ---- Epilogue: bias + relu + store ----
#pragma unroll
        for (int jj = 0; jj < 8; jj++) {
            const int col = 64 * w2 + 8 * jj + 2 * t;
            const float b0 = bsm[col], b1 = bsm[col + 1];
#pragma unroll
            for (int i = 0; i < 4; i++) {
                const int r0 = e0g + 16 * i + g;
                if (r0 < E) {
                    float2 o;
                    o.x = fmaxf(acc[i][jj][0] + b0, 0.f);
                    o.y = fmaxf(acc[i][jj][1] + b1, 0.f);
                    *(float2*)(out + (size_t)r0 * 128 + col) = o;
                }
                if (r0 + 8 < E) {
                    float2 o;
                    o.x = fmaxf(acc[i][jj][2] + b0, 0.f);
                    o.y = fmaxf(acc[i][jj][3] + b1, 0.f);
                    *(float2*)(out + (size_t)(r0 + 8) * 128 + col) = o;
                }
            }
        }

        if (ntile >= ntiles) break;
        tile = ntile; e0g = ne0g;
    }
}

extern "C" void kernel_launch(void* const* d_in, const int* in_sizes, int n_in,
                              void* d_out, int out_size) {
    const float* nf = (const float*)d_in[0];
    const int*   ei = (const int*)d_in[1];
    const float* ef = (const float*)d_in[2];
    const float* W  = (const float*)d_in[3];
    const float* b  = (const float*)d_in[4];
    float* out = (float*)d_out;

    const int E = in_sizes[2] / 128;

    cudaFuncSetAttribute(edge_update_kernel,
                         cudaFuncAttributeMaxDynamicSharedMemorySize, SM_BYTES);

    int dev = 0, sms = 148;
    cudaGetDevice(&dev);
    cudaDeviceGetAttribute(&sms, cudaDevAttrMultiProcessorCount, dev);

    const int ntiles = (E + 255) / 256;
    const int grid = (sms < ntiles) ? sms : ntiles;

    edge_update_kernel<<<grid, 256, SM_BYTES>>>(nf, ei, ef, W, b, out, E);
}

// round 9
// speedup vs baseline: 1.0149x; 1.0149x over previous
#include <cuda_runtime.h>
#include <cstdint>

// ============================================================================
// EdgeUpdate: out[e] = relu( concat(nf[src[e]]+nf[dst[e]], ef[e]) @ W^T + b )
// GEMM: M=E (640000), N=128, K=256. tf32 mma.m16n8k8, fp32 accumulate.
//
// R9 = R8 geometry (4 groups x 2 warps, 64-edge group tiles, 64x64 warp
// tiles, K in 8 sub-phases of 32, double-buffered A) with the register diet
// that removes R8's spills: single x[16] staging buffer, offset-based smem
// addressing. Layouts/swizzles identical to R8 (verified passing).
// ============================================================================

static constexpr int SMB_BIAS = 0;
static constexpr int SMB_W    = 512;                 // 2 x 65536
static constexpr int SMB_A    = 512 + 131072;        // 4 groups x 2 bufs x 8192
static constexpr int SM_BYTES = SMB_A + 4 * 16384;   // 197120

#define CVT_TF32(u, f) asm("cvt.rna.tf32.f32 %0, %1;" : "=r"(u) : "f"(f))

__device__ __forceinline__ void mma_tf32(float* d, uint32_t a0, uint32_t a1,
                                         uint32_t a2, uint32_t a3,
                                         uint32_t b0, uint32_t b1) {
    asm volatile(
        "mma.sync.aligned.m16n8k8.row.col.f32.tf32.tf32.f32 "
        "{%0,%1,%2,%3}, {%4,%5,%6,%7}, {%8,%9}, {%0,%1,%2,%3};"
        : "+f"(d[0]), "+f"(d[1]), "+f"(d[2]), "+f"(d[3])
        : "r"(a0), "r"(a1), "r"(a2), "r"(a3), "r"(b0), "r"(b1));
}

// W store: 128-k rows (8 chunks of 64B), chunk=q^(row&7), slot=t^(((q>>1)+(row>>1))&3)
__device__ __forceinline__ void store_w_chunk(char* wrow, int row, int kbase32,
                                              const float* x) {
    const int r7  = row & 7;
    const int rh2 = (row >> 1) & 3;
#pragma unroll
    for (int qp = 0; qp < 2; qp++) {
        const int q = kbase32 * 2 + qp;
        char* cp = wrow + ((q ^ r7) << 6);
#pragma unroll
        for (int tt = 0; tt < 4; tt++) {
            const int slot = (tt ^ (((q >> 1) + rh2) & 3));
            uint32_t u0, u1, u2, u3;
            CVT_TF32(u0, x[16 * qp + tt]);
            CVT_TF32(u1, x[16 * qp + tt + 4]);
            CVT_TF32(u2, x[16 * qp + tt + 8]);
            CVT_TF32(u3, x[16 * qp + tt + 12]);
            *(uint4*)(cp + slot * 16) = make_uint4(u0, u1, u2, u3);
        }
    }
}

__global__ void __launch_bounds__(256, 1)
edge_update_kernel(const float* __restrict__ nf,
                   const int* __restrict__ ei,      // int32[2*E] (JAX x64 off)
                   const float* __restrict__ ef,
                   const float* __restrict__ W,
                   const float* __restrict__ bias,
                   float* __restrict__ out, int E) {
    extern __shared__ char smem[];
    float* bsm = (float*)(smem + SMB_BIAS);

    const int tid = threadIdx.x;
    const int wid = tid >> 5;
    const int lid = tid & 31;
    const int g   = lid >> 2;
    const int t   = lid & 3;
    const int g1  = g & 1;
    const int gh  = (g >> 1) & 3;
    const int gid = wid >> 1;          // group 0..3
    const int w2  = wid & 1;           // warp in group = N half

    if (tid < 128) bsm[tid] = bias[tid];

    // ---- One-time: W -> packed tf32 smem (2 k-phase arrays) ----
    {
        const int row = tid & 127;
        const int p   = tid >> 7;
        char* wrow = smem + SMB_W + p * 65536 + row * 512;
        const float* src = W + row * 256 + p * 128;
#pragma unroll 1
        for (int c = 0; c < 4; c++) {
            float x[32];
            const float4* sp = (const float4*)(src + c * 32);
#pragma unroll
            for (int i = 0; i < 8; i++) {
                float4 v = sp[i];
                x[4 * i] = v.x; x[4 * i + 1] = v.y;
                x[4 * i + 2] = v.z; x[4 * i + 3] = v.w;
            }
            store_w_chunk(wrow, row, c, x);
        }
    }
    __syncthreads();

    // ---- Fill-side constants ----
    const int r4  = lid >> 3;              // row within 4-row iter
    const int b16 = lid & 7;               // 16B column within 128B (32 k)
    const int qf  = b16 >> 2;
    const uint32_t ebase = (uint32_t)((((((qf ^ (r4 & 1)) << 2) |
                         ((((r4 >> 1) & 1) << 1) ^ qf))) << 4) + (lid & 3) * 4);
    const int fillrow0 = 32 * w2 + r4;     // + 4*idx

    // group A base as generic pointer once; inner addressing via offsets
    char* Ag = smem + SMB_A + gid * 16384;

    // ---- MMA-side constants ----
    const int elo = t ^ (((g >> 1) & 1) << 1);
    const char* aBase = Ag + g * 128;
    const char* wBase = smem + SMB_W + (64 * w2 + g) * 512;
    const int barid = gid + 1;
    const int ntiles = (E + 255) >> 8;

    auto load_idx = [&](int base_e, int* sIl, int* dIl) {
#pragma unroll
        for (int idx = 0; idx < 8; idx++) {
            int e = base_e + fillrow0 + 4 * idx;
            int eg2 = (e < E) ? e : (E - 1);
            sIl[idx] = ei[eg2];
            dIl[idx] = ei[(size_t)E + eg2];
        }
    };
    auto ldg_nf_h = [&](const int* sIl, const int* dIl, int sub, int h, float* x) {
#pragma unroll
        for (int it = 0; it < 4; it++) {
            const int idx = 4 * h + it;
            const float4 a = *(const float4*)(nf + (size_t)sIl[idx] * 128 + sub * 32 + b16 * 4);
            const float4 b = *(const float4*)(nf + (size_t)dIl[idx] * 128 + sub * 32 + b16 * 4);
            x[4 * it]     = a.x + b.x; x[4 * it + 1] = a.y + b.y;
            x[4 * it + 2] = a.z + b.z; x[4 * it + 3] = a.w + b.w;
        }
    };
    auto ldg_ef_h = [&](int base_e, int sp, int h, float* x) {
#pragma unroll
        for (int it = 0; it < 4; it++) {
            const int idx = 4 * h + it;
            int e = base_e + fillrow0 + 4 * idx;
            int eg2 = (e < E) ? e : (E - 1);
            const float4 v = *(const float4*)(ef + (size_t)eg2 * 128 + sp * 32 + b16 * 4);
            x[4 * it]     = v.x; x[4 * it + 1] = v.y;
            x[4 * it + 2] = v.z; x[4 * it + 3] = v.w;
        }
    };
    auto sts_h = [&](int bsel, int h, const float* x) {
        char* base = Ag + bsel * 8192;
#pragma unroll
        for (int it = 0; it < 4; it++) {
            const int row = fillrow0 + 4 * (4 * h + it);
            char* p0 = base + row * 128 + ebase;
#pragma unroll
            for (int j = 0; j < 4; j++) {
                uint32_t u; CVT_TF32(u, x[4 * it + j]);
                *(uint32_t*)((uintptr_t)p0 ^ (unsigned)(j << 4)) = u;
            }
        }
    };
    // MMA one q-step (k=16): A buf bsel chunk q (0/1), W phase wph chunk qg (0..7)
    auto mma_q = [&](int bsel, int q, int wph, int qg, float (*acc)[8][4]) {
        const char* ab = aBase + bsel * 8192;
        const uint32_t eoff = (uint32_t)(((((q ^ g1) << 2) | (elo ^ q))) << 4);
        uint4 aL[4], aH[4];
#pragma unroll
        for (int i = 0; i < 4; i++) {
            aL[i] = *(const uint4*)(ab + i * 2048 + eoff);
            aH[i] = *(const uint4*)(ab + i * 2048 + 1024 + eoff);
        }
        const char* wb = wBase + wph * 65536 + ((qg ^ g) << 6) +
                         ((t ^ (((qg >> 1) + gh) & 3)) << 4);
#pragma unroll
        for (int jj = 0; jj < 8; jj++) {
            const uint4 bv = *(const uint4*)(wb + jj * 4096);
#pragma unroll
            for (int i = 0; i < 4; i++) {
                mma_tf32(acc[i][jj], aL[i].x, aH[i].x, aL[i].y, aH[i].y, bv.x, bv.y);
                mma_tf32(acc[i][jj], aL[i].z, aH[i].z, aL[i].w, aH[i].w, bv.z, bv.w);
            }
        }
    };

    // ---- Prologue: fill buf0 with sub0 (nf k 0-31) ----
    int tile = blockIdx.x;
    if (tile >= ntiles) return;
    int e0g = tile * 256 + gid * 64;
    int sI[8], dI[8];
    load_idx(e0g, sI, dI);
    float x[16];                       // SINGLE staging buffer (R8 had two)
    ldg_nf_h(sI, dI, 0, 0, x); sts_h(0, 0, x);
    ldg_nf_h(sI, dI, 0, 1, x); sts_h(0, 1, x);
    asm volatile("bar.sync %0, 64;" :: "r"(barid) : "memory");

    while (true) {
        float acc[4][8][4] = {};

        // segs 0-2: mma nf sub s; fill nf sub s+1
#pragma unroll
        for (int s = 0; s < 3; s++) {
            ldg_nf_h(sI, dI, s + 1, 0, x);
            mma_q(s & 1, 0, 0, s * 2, acc);
            sts_h((s + 1) & 1, 0, x);
            ldg_nf_h(sI, dI, s + 1, 1, x);
            mma_q(s & 1, 1, 0, s * 2 + 1, acc);
            sts_h((s + 1) & 1, 1, x);
            asm volatile("bar.sync %0, 64;" :: "r"(barid) : "memory");
        }

        // seg 3: mma nf sub3; fill ef sp0; reload indices for NEXT tile
        const int ntile = tile + gridDim.x;
        const int ne0g  = ntile * 256 + gid * 64;
        ldg_ef_h(e0g, 0, 0, x);
        mma_q(1, 0, 0, 6, acc);
        sts_h(0, 0, x);
        ldg_ef_h(e0g, 0, 1, x);
        mma_q(1, 1, 0, 7, acc);
        sts_h(0, 1, x);
        load_idx(ne0g, sI, dI);            // clamped; harmless past end
        asm volatile("bar.sync %0, 64;" :: "r"(barid) : "memory");

        // segs 4-6: mma ef sub s; fill ef sp s-3
#pragma unroll
        for (int s = 4; s < 7; s++) {
            ldg_ef_h(e0g, s - 3, 0, x);
            mma_q(s & 1, 0, 1, (s - 4) * 2, acc);
            sts_h((s + 1) & 1, 0, x);
            ldg_ef_h(e0g, s - 3, 1, x);
            mma_q(s & 1, 1, 1, (s - 4) * 2 + 1, acc);
            sts_h((s + 1) & 1, 1, x);
            asm volatile("bar.sync %0, 64;" :: "r"(barid) : "memory");
        }

        // seg 7: mma ef sub7; fill NEXT tile's nf sub0 -> buf0
        ldg_nf_h(sI, dI, 0, 0, x);
        mma_q(1, 0, 1, 6, acc);
        sts_h(0, 0, x);
        ldg_nf_h(sI, dI, 0, 1, x);
        mma_q(1, 1, 1, 7, acc);
        sts_h(0, 1, x);
        asm volatile("bar.sync %0, 64;" :: "r"(barid) : "memory");

        // ---- Epilogue: bias + relu + store ----
#pragma unroll
        for (int jj = 0; jj < 8; jj++) {
            const int col = 64 * w2 + 8 * jj + 2 * t;
            const float b0 = bsm[col], b1 = bsm[col + 1];
#pragma unroll
            for (int i = 0; i < 4; i++) {
                const int r0 = e0g + 16 * i + g;
                if (r0 < E) {
                    float2 o;
                    o.x = fmaxf(acc[i][jj][0] + b0, 0.f);
                    o.y = fmaxf(acc[i][jj][1] + b1, 0.f);
                    *(float2*)(out + (size_t)r0 * 128 + col) = o;
                }
                if (r0 + 8 < E) {
                    float2 o;
                    o.x = fmaxf(acc[i][jj][2] + b0, 0.f);
                    o.y = fmaxf(acc[i][jj][3] + b1, 0.f);
                    *(float2*)(out + (size_t)(r0 + 8) * 128 + col) = o;
                }
            }
        }

        if (ntile >= ntiles) break;
        tile = ntile; e0g = ne0g;
    }
}

extern "C" void kernel_launch(void* const* d_in, const int* in_sizes, int n_in,
                              void* d_out, int out_size) {
    const float* nf = (const float*)d_in[0];
    const int*   ei = (const int*)d_in[1];
    const float* ef = (const float*)d_in[2];
    const float* W  = (const float*)d_in[3];
    const float* b  = (const float*)d_in[4];
    float* out = (float*)d_out;

    const int E = in_sizes[2] / 128;

    cudaFuncSetAttribute(edge_update_kernel,
                         cudaFuncAttributeMaxDynamicSharedMemorySize, SM_BYTES);

    int dev = 0, sms = 148;
    cudaGetDevice(&dev);
    cudaDeviceGetAttribute(&sms, cudaDevAttrMultiProcessorCount, dev);

    const int ntiles = (E + 255) / 256;
    const int grid = (sms < ntiles) ? sms : ntiles;

    edge_update_kernel<<<grid, 256, SM_BYTES>>>(nf, ei, ef, W, b, out, E);
}

// round 10
// speedup vs baseline: 1.3743x; 1.3541x over previous
#include <cuda_runtime.h>
#include <cuda_fp16.h>
#include <cstdint>

// ============================================================================
// EdgeUpdate: out[e] = relu( concat(nf[src[e]]+nf[dst[e]], ef[e]) @ W^T + b )
// GEMM: M=E (640000), N=128, K=256. fp16 mma.m16n8k16, fp32 accumulate.
// (fp16 mantissa == tf32 mantissa (11 bits) -> same accuracy, half the bytes,
//  half the mma instructions.)
//
// 384 threads = 3 groups x 4 warps; 64-edge group tiles; 64x32 warp tiles.
// K in 8 sub-phases of 32 k, double-buffered A (2 x 4KB per group); fills
// (coalesced LDG.128 -> shfl row-pair exchange -> STS.64) hidden under MMA.
//
// A entry (16B) per (i, g, t, ks): [f16x2(r,2t),(r+8,2t),(r,2t+8),(r+8,2t+8)]
//   = exactly the thread's m16n8k16 A fragment; addr = ks*2048 + i*512 +
//   (g*4+t)*16 + b*8 per 4KB buffer. LDS.128 conflict-free (slot == lid).
// W entry (16B) per (c, p, t): m=0..3 -> f16x2(c, k=32p+2t+8m); addr =
//   (c>>3)*4096 + p*512 + ((c&7)*4+t)*16. One LDS.128 = B frags for 2 ksteps.
// ============================================================================

static constexpr int SMB_BIAS = 0;
static constexpr int SMB_W    = 512;                  // 64 KB
static constexpr int SMB_A    = 512 + 65536;          // 3 groups x 2 x 4096
static constexpr int SM_BYTES = SMB_A + 3 * 8192;     // 90624

__device__ __forceinline__ void mma_f16(float* d, uint32_t a0, uint32_t a1,
                                        uint32_t a2, uint32_t a3,
                                        uint32_t b0, uint32_t b1) {
    asm volatile(
        "mma.sync.aligned.m16n8k16.row.col.f32.f16.f16.f32 "
        "{%0,%1,%2,%3}, {%4,%5,%6,%7}, {%8,%9}, {%0,%1,%2,%3};"
        : "+f"(d[0]), "+f"(d[1]), "+f"(d[2]), "+f"(d[3])
        : "r"(a0), "r"(a1), "r"(a2), "r"(a3), "r"(b0), "r"(b1));
}

__device__ __forceinline__ uint32_t h2(float lo, float hi) {
    __half2 v = __floats2half2_rn(lo, hi);
    return *reinterpret_cast<uint32_t*>(&v);
}

__global__ void __launch_bounds__(384, 1)
edge_update_kernel(const float* __restrict__ nf,
                   const int* __restrict__ ei,      // int32[2*E] (JAX x64 off)
                   const float* __restrict__ ef,
                   const float* __restrict__ W,
                   const float* __restrict__ bias,
                   float* __restrict__ out, int E) {
    extern __shared__ char smem[];
    float* bsm = (float*)(smem + SMB_BIAS);

    const int tid = threadIdx.x;
    const int wid = tid >> 5;
    const int lid = tid & 31;
    const int g   = lid >> 2;          // 0..7
    const int t   = lid & 3;           // 0..3
    const int gid = wid >> 2;          // group 0..2
    const int w4  = wid & 3;           // warp in group = N strip
    const int nw  = w4 * 32;

    if (tid < 128) bsm[tid] = bias[tid];

    // ---- One-time: W -> packed fp16 smem ----
    for (int task = tid; task < 1024; task += 384) {
        const int c = task >> 3, p = task & 7;
        const float* src = W + c * 256 + p * 32;
        float x[32];
#pragma unroll
        for (int i = 0; i < 8; i++) {
            float4 v = ((const float4*)src)[i];
            x[4 * i] = v.x; x[4 * i + 1] = v.y;
            x[4 * i + 2] = v.z; x[4 * i + 3] = v.w;
        }
        char* base = smem + SMB_W + (c >> 3) * 4096 + p * 512 + (c & 7) * 64;
#pragma unroll
        for (int tt = 0; tt < 4; tt++)
#pragma unroll
            for (int m = 0; m < 4; m++)
                *(uint32_t*)(base + tt * 16 + m * 4) =
                    h2(x[2 * tt + 8 * m], x[2 * tt + 8 * m + 1]);
    }
    __syncthreads();

    // ---- Fill-side constants ----
    const int fc = lid & 7;                 // 16B k-chunk (4 floats)
    const int hl = (lid >> 3) & 1;          // row-pair half (+8)
    const int rr = (lid >> 4) & 1;
    const int rowoff = 2 * w4 + rr + 8 * hl;    // + 16*it
    // STS.64 target (per it): entry(t=2*(fc&1)+hl, g=2w+rr, ks=fc>>2, b=(fc>>1)&1)
    const uint32_t sts_off = (uint32_t)((fc >> 2) * 2048 +
                             ((2 * w4 + rr) * 4 + 2 * (fc & 1) + hl) * 16 +
                             ((fc >> 1) & 1) * 8);

    char* Ag = smem + SMB_A + gid * 8192;   // 2 buffers of 4096

    // ---- MMA-side constants ----
    const char* aBase = Ag + (g * 4 + t) * 16;
    const char* wBase = smem + SMB_W + (nw >> 3) * 4096 + (g * 4 + t) * 16;
    const int barid = gid + 1;
    const int ntiles = (E + 191) / 192;

    auto load_idx = [&](int base_e, int* sI, int* dI) {
#pragma unroll
        for (int it = 0; it < 4; it++) {
            int e = base_e + rowoff + 16 * it;
            int eg2 = (e < E) ? e : (E - 1);
            sI[it] = ei[eg2];
            dI[it] = ei[(size_t)E + eg2];
        }
    };
    auto ldg_nf = [&](const int* sI, const int* dI, int sub, float* x) {
#pragma unroll
        for (int it = 0; it < 4; it++) {
            const float4 a = *(const float4*)(nf + (size_t)sI[it] * 128 + sub * 32 + fc * 4);
            const float4 b = *(const float4*)(nf + (size_t)dI[it] * 128 + sub * 32 + fc * 4);
            x[4 * it]     = a.x + b.x; x[4 * it + 1] = a.y + b.y;
            x[4 * it + 2] = a.z + b.z; x[4 * it + 3] = a.w + b.w;
        }
    };
    auto ldg_ef = [&](int base_e, int sub, float* x) {
#pragma unroll
        for (int it = 0; it < 4; it++) {
            int e = base_e + rowoff + 16 * it;
            int eg2 = (e < E) ? e : (E - 1);
            const float4 v = *(const float4*)(ef + (size_t)eg2 * 128 + sub * 32 + fc * 4);
            x[4 * it]     = v.x; x[4 * it + 1] = v.y;
            x[4 * it + 2] = v.z; x[4 * it + 3] = v.w;
        }
    };
    // convert + row-pair shuffle + STS.64 scatter into buffer bsel
    auto sts_x = [&](int bsel, const float* x) {
        char* base = Ag + bsel * 4096 + sts_off;
#pragma unroll
        for (int it = 0; it < 4; it++) {
            const uint32_t v0 = h2(x[4 * it], x[4 * it + 1]);
            const uint32_t v1 = h2(x[4 * it + 2], x[4 * it + 3]);
            const uint32_t r0 = __shfl_xor_sync(0xFFFFFFFFu, v0, 8);
            const uint32_t r1 = __shfl_xor_sync(0xFFFFFFFFu, v1, 8);
            const uint2 val = hl ? make_uint2(r1, v1) : make_uint2(v0, r0);
            *(uint2*)(base + it * 512) = val;
        }
    };
    // MMA one sub-phase (= W kpair p = 2 k-steps) on A buffer bsel
    auto mma_sub = [&](int bsel, int p, float (*acc)[4][4]) {
        uint4 bv[4];
#pragma unroll
        for (int j = 0; j < 4; j++)
            bv[j] = *(const uint4*)(wBase + j * 4096 + p * 512);
        const char* ab = aBase + bsel * 4096;
#pragma unroll
        for (int sp = 0; sp < 2; sp++) {
            uint4 av[4];
#pragma unroll
            for (int i = 0; i < 4; i++)
                av[i] = *(const uint4*)(ab + sp * 2048 + i * 512);
#pragma unroll
            for (int i = 0; i < 4; i++)
#pragma unroll
                for (int j = 0; j < 4; j++)
                    mma_f16(acc[i][j], av[i].x, av[i].y, av[i].z, av[i].w,
                            sp ? bv[j].z : bv[j].x, sp ? bv[j].w : bv[j].y);
        }
    };

    // ---- Prologue: fill buf0 with nf sub0 (k 0-31) ----
    int tile = blockIdx.x;
    if (tile >= ntiles) return;
    int e0g = tile * 192 + gid * 64;
    int sI[4], dI[4];
    load_idx(e0g, sI, dI);
    float x[16];
    ldg_nf(sI, dI, 0, x);
    sts_x(0, x);
    asm volatile("bar.sync %0, 128;" :: "r"(barid) : "memory");

    while (true) {
        float acc[4][4][4] = {};

        // s=0..2: mma nf sub s; fill nf sub s+1
#pragma unroll
        for (int s = 0; s < 3; s++) {
            ldg_nf(sI, dI, s + 1, x);
            mma_sub(s & 1, s, acc);
            sts_x((s + 1) & 1, x);
            asm volatile("bar.sync %0, 128;" :: "r"(barid) : "memory");
        }

        // s=3: mma nf sub3; fill ef sub0; reload indices for NEXT tile
        const int ntile = tile + gridDim.x;
        const int ne0g  = ntile * 192 + gid * 64;
        ldg_ef(e0g, 0, x);
        mma_sub(1, 3, acc);
        sts_x(0, x);
        load_idx(ne0g, sI, dI);            // clamped; harmless past end
        asm volatile("bar.sync %0, 128;" :: "r"(barid) : "memory");

        // s=4..6: mma ef sub s-4; fill ef sub s-3
#pragma unroll
        for (int s = 4; s < 7; s++) {
            ldg_ef(e0g, s - 3, x);
            mma_sub(s & 1, s, acc);
            sts_x((s + 1) & 1, x);
            asm volatile("bar.sync %0, 128;" :: "r"(barid) : "memory");
        }

        // s=7: mma ef sub3; fill NEXT tile's nf sub0 -> buf0
        ldg_nf(sI, dI, 0, x);
        mma_sub(1, 7, acc);
        sts_x(0, x);
        asm volatile("bar.sync %0, 128;" :: "r"(barid) : "memory");

        // ---- Epilogue: bias + relu + store ----
#pragma unroll
        for (int j = 0; j < 4; j++) {
            const int col = nw + 8 * j + 2 * t;
            const float b0 = bsm[col], b1 = bsm[col + 1];
#pragma unroll
            for (int i = 0; i < 4; i++) {
                const int r0 = e0g + 16 * i + g;
                if (r0 < E) {
                    float2 o;
                    o.x = fmaxf(acc[i][j][0] + b0, 0.f);
                    o.y = fmaxf(acc[i][j][1] + b1, 0.f);
                    *(float2*)(out + (size_t)r0 * 128 + col) = o;
                }
                if (r0 + 8 < E) {
                    float2 o;
                    o.x = fmaxf(acc[i][j][2] + b0, 0.f);
                    o.y = fmaxf(acc[i][j][3] + b1, 0.f);
                    *(float2*)(out + (size_t)(r0 + 8) * 128 + col) = o;
                }
            }
        }

        if (ntile >= ntiles) break;
        tile = ntile; e0g = ne0g;
    }
}

extern "C" void kernel_launch(void* const* d_in, const int* in_sizes, int n_in,
                              void* d_out, int out_size) {
    const float* nf = (const float*)d_in[0];
    const int*   ei = (const int*)d_in[1];
    const float* ef = (const float*)d_in[2];
    const float* W  = (const float*)d_in[3];
    const float* b  = (const float*)d_in[4];
    float* out = (float*)d_out;

    const int E = in_sizes[2] / 128;

    cudaFuncSetAttribute(edge_update_kernel,
                         cudaFuncAttributeMaxDynamicSharedMemorySize, SM_BYTES);

    int dev = 0, sms = 148;
    cudaGetDevice(&dev);
    cudaDeviceGetAttribute(&sms, cudaDevAttrMultiProcessorCount, dev);

    const int ntiles = (E + 191) / 192;
    const int grid = (sms < ntiles) ? sms : ntiles;

    edge_update_kernel<<<grid, 384, SM_BYTES>>>(nf, ei, ef, W, b, out, E);
}

// round 11
// speedup vs baseline: 1.4133x; 1.0284x over previous
#include <cuda_runtime.h>
#include <cuda_fp16.h>
#include <cstdint>

// ============================================================================
// EdgeUpdate: out[e] = relu( concat(nf[src[e]]+nf[dst[e]], ef[e]) @ W^T + b )
// GEMM: M=E (640000), N=128, K=256. fp16 mma.m16n8k16, fp32 accumulate.
//
// R11 = R10 structure at 512 threads (4 groups x 4 warps, occ 25%): same
// 64-edge group tiles, 64x32 warp tiles, 8 sub-phases of 32 k, double-
// buffered A. Register diet to fit the 128-reg cap: no sI/dI index arrays
// (fills load their indices inline; L1-resident), no cross-tile idx prefetch.
//
// A entry (16B) per (i, g, t, ks): exactly the thread's m16n8k16 A fragment;
//   addr = ks*2048 + i*512 + (g*4+t)*16 (+8 per half) per 4KB buffer.
// W entry (16B) per (c, p, t): m=0..3 -> f16x2(c, k=32p+2t+8m); addr =
//   (c>>3)*4096 + p*512 + ((c&7)*4+t)*16. One LDS.128 = B frags for 2 ksteps.
// ============================================================================

static constexpr int SMB_BIAS = 0;
static constexpr int SMB_W    = 512;                  // 64 KB
static constexpr int SMB_A    = 512 + 65536;          // 4 groups x 2 x 4096
static constexpr int SM_BYTES = SMB_A + 4 * 8192;     // 98816

__device__ __forceinline__ void mma_f16(float* d, uint32_t a0, uint32_t a1,
                                        uint32_t a2, uint32_t a3,
                                        uint32_t b0, uint32_t b1) {
    asm volatile(
        "mma.sync.aligned.m16n8k16.row.col.f32.f16.f16.f32 "
        "{%0,%1,%2,%3}, {%4,%5,%6,%7}, {%8,%9}, {%0,%1,%2,%3};"
        : "+f"(d[0]), "+f"(d[1]), "+f"(d[2]), "+f"(d[3])
        : "r"(a0), "r"(a1), "r"(a2), "r"(a3), "r"(b0), "r"(b1));
}

__device__ __forceinline__ uint32_t h2(float lo, float hi) {
    __half2 v = __floats2half2_rn(lo, hi);
    return *reinterpret_cast<uint32_t*>(&v);
}

__global__ void __launch_bounds__(512, 1)
edge_update_kernel(const float* __restrict__ nf,
                   const int* __restrict__ ei,      // int32[2*E] (JAX x64 off)
                   const float* __restrict__ ef,
                   const float* __restrict__ W,
                   const float* __restrict__ bias,
                   float* __restrict__ out, int E) {
    extern __shared__ char smem[];
    float* bsm = (float*)(smem + SMB_BIAS);

    const int tid = threadIdx.x;
    const int wid = tid >> 5;
    const int lid = tid & 31;
    const int g   = lid >> 2;          // 0..7
    const int t   = lid & 3;           // 0..3
    const int gid = wid >> 2;          // group 0..3
    const int w4  = wid & 3;           // warp in group = N strip
    const int nw  = w4 * 32;

    if (tid < 128) bsm[tid] = bias[tid];

    // ---- One-time: W -> packed fp16 smem ----
    for (int task = tid; task < 1024; task += 512) {
        const int c = task >> 3, p = task & 7;
        const float* src = W + c * 256 + p * 32;
        float x[32];
#pragma unroll
        for (int i = 0; i < 8; i++) {
            float4 v = ((const float4*)src)[i];
            x[4 * i] = v.x; x[4 * i + 1] = v.y;
            x[4 * i + 2] = v.z; x[4 * i + 3] = v.w;
        }
        char* base = smem + SMB_W + (c >> 3) * 4096 + p * 512 + (c & 7) * 64;
#pragma unroll
        for (int tt = 0; tt < 4; tt++)
#pragma unroll
            for (int m = 0; m < 4; m++)
                *(uint32_t*)(base + tt * 16 + m * 4) =
                    h2(x[2 * tt + 8 * m], x[2 * tt + 8 * m + 1]);
    }
    __syncthreads();

    // ---- Fill-side constants ----
    const int fc = lid & 7;                 // 16B k-chunk (4 floats)
    const int hl = (lid >> 3) & 1;          // row-pair half (+8)
    const int rr = (lid >> 4) & 1;
    const int rowoff = 2 * w4 + rr + 8 * hl;    // + 16*it
    const uint32_t sts_off = (uint32_t)((fc >> 2) * 2048 +
                             ((2 * w4 + rr) * 4 + 2 * (fc & 1) + hl) * 16 +
                             ((fc >> 1) & 1) * 8);

    char* Ag = smem + SMB_A + gid * 8192;   // 2 buffers of 4096

    // ---- MMA-side constants ----
    const char* aBase = Ag + (g * 4 + t) * 16;
    const char* wBase = smem + SMB_W + (nw >> 3) * 4096 + (g * 4 + t) * 16;
    const int barid = gid + 1;
    const int ntiles = (E + 255) >> 8;

    // fills load their own indices (L1-resident; dependency sits on hidden path)
    auto ldg_nf = [&](int base_e, int sub, float* x) {
#pragma unroll
        for (int it = 0; it < 4; it++) {
            int e = base_e + rowoff + 16 * it;
            int eg2 = (e < E) ? e : (E - 1);
            const int s  = ei[eg2];
            const int dd = ei[(size_t)E + eg2];
            const float4 a = *(const float4*)(nf + (size_t)s  * 128 + sub * 32 + fc * 4);
            const float4 b = *(const float4*)(nf + (size_t)dd * 128 + sub * 32 + fc * 4);
            x[4 * it]     = a.x + b.x; x[4 * it + 1] = a.y + b.y;
            x[4 * it + 2] = a.z + b.z; x[4 * it + 3] = a.w + b.w;
        }
    };
    auto ldg_ef = [&](int base_e, int sub, float* x) {
#pragma unroll
        for (int it = 0; it < 4; it++) {
            int e = base_e + rowoff + 16 * it;
            int eg2 = (e < E) ? e : (E - 1);
            const float4 v = *(const float4*)(ef + (size_t)eg2 * 128 + sub * 32 + fc * 4);
            x[4 * it]     = v.x; x[4 * it + 1] = v.y;
            x[4 * it + 2] = v.z; x[4 * it + 3] = v.w;
        }
    };
    // convert + row-pair shuffle + STS.64 scatter into buffer bsel
    auto sts_x = [&](int bsel, const float* x) {
        char* base = Ag + bsel * 4096 + sts_off;
#pragma unroll
        for (int it = 0; it < 4; it++) {
            const uint32_t v0 = h2(x[4 * it], x[4 * it + 1]);
            const uint32_t v1 = h2(x[4 * it + 2], x[4 * it + 3]);
            const uint32_t r0 = __shfl_xor_sync(0xFFFFFFFFu, v0, 8);
            const uint32_t r1 = __shfl_xor_sync(0xFFFFFFFFu, v1, 8);
            const uint2 val = hl ? make_uint2(r1, v1) : make_uint2(v0, r0);
            *(uint2*)(base + it * 512) = val;
        }
    };
    // MMA one sub-phase (= W kpair p = 2 k-steps) on A buffer bsel
    auto mma_sub = [&](int bsel, int p, float (*acc)[4][4]) {
        uint4 bv[4];
#pragma unroll
        for (int j = 0; j < 4; j++)
            bv[j] = *(const uint4*)(wBase + j * 4096 + p * 512);
        const char* ab = aBase + bsel * 4096;
#pragma unroll
        for (int sp = 0; sp < 2; sp++) {
            uint4 av[4];
#pragma unroll
            for (int i = 0; i < 4; i++)
                av[i] = *(const uint4*)(ab + sp * 2048 + i * 512);
#pragma unroll
            for (int i = 0; i < 4; i++)
#pragma unroll
                for (int j = 0; j < 4; j++)
                    mma_f16(acc[i][j], av[i].x, av[i].y, av[i].z, av[i].w,
                            sp ? bv[j].z : bv[j].x, sp ? bv[j].w : bv[j].y);
        }
    };

    // ---- Prologue: fill buf0 with nf sub0 (k 0-31) ----
    int tile = blockIdx.x;
    if (tile >= ntiles) return;
    int e0g = tile * 256 + gid * 64;
    float x[16];
    ldg_nf(e0g, 0, x);
    sts_x(0, x);
    asm volatile("bar.sync %0, 128;" :: "r"(barid) : "memory");

    while (true) {
        float acc[4][4][4] = {};

        // s=0..2: mma nf sub s; fill nf sub s+1
#pragma unroll
        for (int s = 0; s < 3; s++) {
            ldg_nf(e0g, s + 1, x);
            mma_sub(s & 1, s, acc);
            sts_x((s + 1) & 1, x);
            asm volatile("bar.sync %0, 128;" :: "r"(barid) : "memory");
        }

        // s=3: mma nf sub3; fill ef sub0
        ldg_ef(e0g, 0, x);
        mma_sub(1, 3, acc);
        sts_x(0, x);
        asm volatile("bar.sync %0, 128;" :: "r"(barid) : "memory");

        // s=4..6: mma ef sub s-4; fill ef sub s-3
#pragma unroll
        for (int s = 4; s < 7; s++) {
            ldg_ef(e0g, s - 3, x);
            mma_sub(s & 1, s, acc);
            sts_x((s + 1) & 1, x);
            asm volatile("bar.sync %0, 128;" :: "r"(barid) : "memory");
        }

        // s=7: mma ef sub3; fill NEXT tile's nf sub0 -> buf0
        const int ntile = tile + gridDim.x;
        const int ne0g  = ntile * 256 + gid * 64;
        ldg_nf((ntile < ntiles) ? ne0g : 0, 0, x);   // clamped fill if past end
        mma_sub(1, 7, acc);
        sts_x(0, x);
        asm volatile("bar.sync %0, 128;" :: "r"(barid) : "memory");

        // ---- Epilogue: bias + relu + store ----
#pragma unroll
        for (int j = 0; j < 4; j++) {
            const int col = nw + 8 * j + 2 * t;
            const float b0 = bsm[col], b1 = bsm[col + 1];
#pragma unroll
            for (int i = 0; i < 4; i++) {
                const int r0 = e0g + 16 * i + g;
                if (r0 < E) {
                    float2 o;
                    o.x = fmaxf(acc[i][j][0] + b0, 0.f);
                    o.y = fmaxf(acc[i][j][1] + b1, 0.f);
                    *(float2*)(out + (size_t)r0 * 128 + col) = o;
                }
                if (r0 + 8 < E) {
                    float2 o;
                    o.x = fmaxf(acc[i][j][2] + b0, 0.f);
                    o.y = fmaxf(acc[i][j][3] + b1, 0.f);
                    *(float2*)(out + (size_t)(r0 + 8) * 128 + col) = o;
                }
            }
        }

        if (ntile >= ntiles) break;
        tile = ntile; e0g = ne0g;
    }
}

extern "C" void kernel_launch(void* const* d_in, const int* in_sizes, int n_in,
                              void* d_out, int out_size) {
    const float* nf = (const float*)d_in[0];
    const int*   ei = (const int*)d_in[1];
    const float* ef = (const float*)d_in[2];
    const float* W  = (const float*)d_in[3];
    const float* b  = (const float*)d_in[4];
    float* out = (float*)d_out;

    const int E = in_sizes[2] / 128;

    cudaFuncSetAttribute(edge_update_kernel,
                         cudaFuncAttributeMaxDynamicSharedMemorySize, SM_BYTES);

    int dev = 0, sms = 148;
    cudaGetDevice(&dev);
    cudaDeviceGetAttribute(&sms, cudaDevAttrMultiProcessorCount, dev);

    const int ntiles = (E + 255) / 256;
    const int grid = (sms < ntiles) ? sms : ntiles;

    edge_update_kernel<<<grid, 512, SM_BYTES>>>(nf, ei, ef, W, b, out, E);
}

// round 12
// speedup vs baseline: 1.6757x; 1.1856x over previous
#include <cuda_runtime.h>
#include <cuda_fp16.h>
#include <cstdint>

// ============================================================================
// EdgeUpdate: out[e] = relu( concat(nf[src[e]]+nf[dst[e]], ef[e]) @ W^T + b )
// GEMM: M=E (640000), N=128, K=256. fp16 mma.m16n8k16, fp32 accumulate.
//
// R12 = R11 with a 4-deep A ring per group (4 x 4KB): at segment s we
//   STS data loaded during segment s-1  -> buf[(s+1)&3]
//   LDG data for segment s+2            -> x
//   MMA on buf[s&3]
//   bar
// so every LDG has a FULL segment (+barrier) before its STS -> fill latency
// (L2 ~234x2 chained, ef DRAM ~400-600) never reaches the barrier.
// 8 segs/tile = 0 mod 4 -> buffer phase aligns across tiles automatically.
// Layouts, MMA, epilogue identical to R11 (passing, rel_err 2.78e-4).
// ============================================================================

static constexpr int SMB_BIAS = 0;
static constexpr int SMB_W    = 512;                  // 64 KB
static constexpr int SMB_A    = 512 + 65536;          // 4 groups x 4 x 4096
static constexpr int SM_BYTES = SMB_A + 4 * 16384;    // 131584

__device__ __forceinline__ void mma_f16(float* d, uint32_t a0, uint32_t a1,
                                        uint32_t a2, uint32_t a3,
                                        uint32_t b0, uint32_t b1) {
    asm volatile(
        "mma.sync.aligned.m16n8k16.row.col.f32.f16.f16.f32 "
        "{%0,%1,%2,%3}, {%4,%5,%6,%7}, {%8,%9}, {%0,%1,%2,%3};"
        : "+f"(d[0]), "+f"(d[1]), "+f"(d[2]), "+f"(d[3])
        : "r"(a0), "r"(a1), "r"(a2), "r"(a3), "r"(b0), "r"(b1));
}

__device__ __forceinline__ uint32_t h2(float lo, float hi) {
    __half2 v = __floats2half2_rn(lo, hi);
    return *reinterpret_cast<uint32_t*>(&v);
}

__global__ void __launch_bounds__(512, 1)
edge_update_kernel(const float* __restrict__ nf,
                   const int* __restrict__ ei,      // int32[2*E] (JAX x64 off)
                   const float* __restrict__ ef,
                   const float* __restrict__ W,
                   const float* __restrict__ bias,
                   float* __restrict__ out, int E) {
    extern __shared__ char smem[];
    float* bsm = (float*)(smem + SMB_BIAS);

    const int tid = threadIdx.x;
    const int wid = tid >> 5;
    const int lid = tid & 31;
    const int g   = lid >> 2;          // 0..7
    const int t   = lid & 3;           // 0..3
    const int gid = wid >> 2;          // group 0..3
    const int w4  = wid & 3;           // warp in group = N strip
    const int nw  = w4 * 32;

    if (tid < 128) bsm[tid] = bias[tid];

    // ---- One-time: W -> packed fp16 smem ----
    for (int task = tid; task < 1024; task += 512) {
        const int c = task >> 3, p = task & 7;
        const float* src = W + c * 256 + p * 32;
        float x[32];
#pragma unroll
        for (int i = 0; i < 8; i++) {
            float4 v = ((const float4*)src)[i];
            x[4 * i] = v.x; x[4 * i + 1] = v.y;
            x[4 * i + 2] = v.z; x[4 * i + 3] = v.w;
        }
        char* base = smem + SMB_W + (c >> 3) * 4096 + p * 512 + (c & 7) * 64;
#pragma unroll
        for (int tt = 0; tt < 4; tt++)
#pragma unroll
            for (int m = 0; m < 4; m++)
                *(uint32_t*)(base + tt * 16 + m * 4) =
                    h2(x[2 * tt + 8 * m], x[2 * tt + 8 * m + 1]);
    }
    __syncthreads();

    // ---- Fill-side constants ----
    const int fc = lid & 7;                 // 16B k-chunk (4 floats)
    const int hl = (lid >> 3) & 1;          // row-pair half (+8)
    const int rr = (lid >> 4) & 1;
    const int rowoff = 2 * w4 + rr + 8 * hl;    // + 16*it
    const uint32_t sts_off = (uint32_t)((fc >> 2) * 2048 +
                             ((2 * w4 + rr) * 4 + 2 * (fc & 1) + hl) * 16 +
                             ((fc >> 1) & 1) * 8);

    char* Ag = smem + SMB_A + gid * 16384;  // 4 buffers of 4096

    // ---- MMA-side constants ----
    const char* aBase = Ag + (g * 4 + t) * 16;
    const char* wBase = smem + SMB_W + (nw >> 3) * 4096 + (g * 4 + t) * 16;
    const int barid = gid + 1;
    const int ntiles = (E + 255) >> 8;

    auto ldg_nf = [&](int base_e, int sub, float* x) {
#pragma unroll
        for (int it = 0; it < 4; it++) {
            int e = base_e + rowoff + 16 * it;
            int eg2 = (e < E) ? e : (E - 1);
            const int s  = ei[eg2];
            const int dd = ei[(size_t)E + eg2];
            const float4 a = *(const float4*)(nf + (size_t)s  * 128 + sub * 32 + fc * 4);
            const float4 b = *(const float4*)(nf + (size_t)dd * 128 + sub * 32 + fc * 4);
            x[4 * it]     = a.x + b.x; x[4 * it + 1] = a.y + b.y;
            x[4 * it + 2] = a.z + b.z; x[4 * it + 3] = a.w + b.w;
        }
    };
    auto ldg_ef = [&](int base_e, int sub, float* x) {
#pragma unroll
        for (int it = 0; it < 4; it++) {
            int e = base_e + rowoff + 16 * it;
            int eg2 = (e < E) ? e : (E - 1);
            const float4 v = *(const float4*)(ef + (size_t)eg2 * 128 + sub * 32 + fc * 4);
            x[4 * it]     = v.x; x[4 * it + 1] = v.y;
            x[4 * it + 2] = v.z; x[4 * it + 3] = v.w;
        }
    };
    // convert + row-pair shuffle + STS.64 scatter into ring buffer bsel
    auto sts_x = [&](int bsel, const float* x) {
        char* base = Ag + bsel * 4096 + sts_off;
#pragma unroll
        for (int it = 0; it < 4; it++) {
            const uint32_t v0 = h2(x[4 * it], x[4 * it + 1]);
            const uint32_t v1 = h2(x[4 * it + 2], x[4 * it + 3]);
            const uint32_t r0 = __shfl_xor_sync(0xFFFFFFFFu, v0, 8);
            const uint32_t r1 = __shfl_xor_sync(0xFFFFFFFFu, v1, 8);
            const uint2 val = hl ? make_uint2(r1, v1) : make_uint2(v0, r0);
            *(uint2*)(base + it * 512) = val;
        }
    };
    // MMA one sub-phase (= W kpair p = 2 k-steps) on A ring buffer bsel
    auto mma_sub = [&](int bsel, int p, float (*acc)[4][4]) {
        uint4 bv[4];
#pragma unroll
        for (int j = 0; j < 4; j++)
            bv[j] = *(const uint4*)(wBase + j * 4096 + p * 512);
        const char* ab = aBase + bsel * 4096;
#pragma unroll
        for (int sp = 0; sp < 2; sp++) {
            uint4 av[4];
#pragma unroll
            for (int i = 0; i < 4; i++)
                av[i] = *(const uint4*)(ab + sp * 2048 + i * 512);
#pragma unroll
            for (int i = 0; i < 4; i++)
#pragma unroll
                for (int j = 0; j < 4; j++)
                    mma_f16(acc[i][j], av[i].x, av[i].y, av[i].z, av[i].w,
                            sp ? bv[j].z : bv[j].x, sp ? bv[j].w : bv[j].y);
        }
    };
    // fill data for segment seg (0..3 = nf sub, 4..7 = ef sub) of tile base
    auto ldg_seg = [&](int base_e, int seg, float* x) {
        if (seg < 4) ldg_nf(base_e, seg, x);
        else         ldg_ef(base_e, seg - 4, x);
    };

    // ---- Prologue: buf0 <- DATA(0); x <- DATA(1) ----
    int tile = blockIdx.x;
    if (tile >= ntiles) return;
    int e0g = tile * 256 + gid * 64;
    float x[16];
    ldg_nf(e0g, 0, x);
    sts_x(0, x);
    ldg_nf(e0g, 1, x);
    asm volatile("bar.sync %0, 128;" :: "r"(barid) : "memory");

    while (true) {
        float acc[4][4][4] = {};
        const int ntile = tile + gridDim.x;
        const int ne0g  = ntile * 256 + gid * 64;
        const int nbase = (ntile < ntiles) ? ne0g : 0;   // clamped prefetch base

        // s = 0..5: sts DATA(s+1); ldg DATA(s+2) [this tile]; mma buf[s&3]
#pragma unroll
        for (int s = 0; s < 6; s++) {
            sts_x((s + 1) & 3, x);
            ldg_seg(e0g, s + 2, x);
            mma_sub(s & 3, s, acc);
            asm volatile("bar.sync %0, 128;" :: "r"(barid) : "memory");
        }
        // s = 6: sts DATA(7); ldg NEXT tile seg0 (nf sub0); mma buf[2]
        sts_x(3, x);
        ldg_nf(nbase, 0, x);
        mma_sub(2, 6, acc);
        asm volatile("bar.sync %0, 128;" :: "r"(barid) : "memory");
        // s = 7: sts NEXT seg0 -> buf0; ldg NEXT seg1 (nf sub1); mma buf[3]
        sts_x(0, x);
        ldg_nf(nbase, 1, x);
        mma_sub(3, 7, acc);
        asm volatile("bar.sync %0, 128;" :: "r"(barid) : "memory");

        // ---- Epilogue: bias + relu + store ----
#pragma unroll
        for (int j = 0; j < 4; j++) {
            const int col = nw + 8 * j + 2 * t;
            const float b0 = bsm[col], b1 = bsm[col + 1];
#pragma unroll
            for (int i = 0; i < 4; i++) {
                const int r0 = e0g + 16 * i + g;
                if (r0 < E) {
                    float2 o;
                    o.x = fmaxf(acc[i][j][0] + b0, 0.f);
                    o.y = fmaxf(acc[i][j][1] + b1, 0.f);
                    *(float2*)(out + (size_t)r0 * 128 + col) = o;
                }
                if (r0 + 8 < E) {
                    float2 o;
                    o.x = fmaxf(acc[i][j][2] + b0, 0.f);
                    o.y = fmaxf(acc[i][j][3] + b1, 0.f);
                    *(float2*)(out + (size_t)(r0 + 8) * 128 + col) = o;
                }
            }
        }

        if (ntile >= ntiles) break;
        tile = ntile; e0g = ne0g;
    }
}

extern "C" void kernel_launch(void* const* d_in, const int* in_sizes, int n_in,
                              void* d_out, int out_size) {
    const float* nf = (const float*)d_in[0];
    const int*   ei = (const int*)d_in[1];
    const float* ef = (const float*)d_in[2];
    const float* W  = (const float*)d_in[3];
    const float* b  = (const float*)d_in[4];
    float* out = (float*)d_out;

    const int E = in_sizes[2] / 128;

    cudaFuncSetAttribute(edge_update_kernel,
                         cudaFuncAttributeMaxDynamicSharedMemorySize, SM_BYTES);

    int dev = 0, sms = 148;
    cudaGetDevice(&dev);
    cudaDeviceGetAttribute(&sms, cudaDevAttrMultiProcessorCount, dev);

    const int ntiles = (E + 255) / 256;
    const int grid = (sms < ntiles) ? sms : ntiles;

    edge_update_kernel<<<grid, 512, SM_BYTES>>>(nf, ei, ef, W, b, out, E);
}